// round 1
// baseline (speedup 1.0000x reference)
#include <cuda_runtime.h>

// Depthwise Conv1d: B=32, C=128, L=8192, kernel=3, stride=1, pad=1, fp32.
// out[b,c,l] = w[c,0]*x[b,c,l-1] + w[c,1]*x[b,c,l] + w[c,2]*x[b,c,l+1] + bias[c]
// (zero padding at row boundaries)
//
// Pure HBM-streaming kernel: one float4 per thread + 2 scalar halo loads
// (L1 hits). Each block stays within one (b,c) row so weight/bias loads
// broadcast.

#define BATCH 32
#define CHANS 128
#define LEN   8192
#define LEN4  (LEN / 4)          // 2048 float4 per row
#define ROWS  (BATCH * CHANS)    // 4096
#define NTHREADS 256

__global__ __launch_bounds__(NTHREADS)
void dwconv1d_kernel(const float* __restrict__ x,
                     const float* __restrict__ w,
                     const float* __restrict__ bias,
                     float* __restrict__ out)
{
    // global float4 index
    unsigned int gid = blockIdx.x * NTHREADS + threadIdx.x;

    unsigned int row = gid >> 11;        // / LEN4
    unsigned int j   = gid & (LEN4 - 1); // within-row float4 index
    unsigned int c   = row & (CHANS - 1);

    // Per-channel taps: uniform within a block -> L1 broadcast
    const float w0 = __ldg(&w[c * 3 + 0]);
    const float w1 = __ldg(&w[c * 3 + 1]);
    const float w2 = __ldg(&w[c * 3 + 2]);
    const float bb = __ldg(&bias[c]);

    const float4* xrow = reinterpret_cast<const float4*>(x) + (size_t)row * LEN4;
    const float*  xs   = reinterpret_cast<const float*>(xrow);

    float4 v = __ldg(&xrow[j]);
    float left  = (j == 0)        ? 0.0f : __ldg(&xs[4u * j - 1]);
    float right = (j == LEN4 - 1) ? 0.0f : __ldg(&xs[4u * j + 4]);

    float4 o;
    o.x = fmaf(w0, left, fmaf(w1, v.x, fmaf(w2, v.y, bb)));
    o.y = fmaf(w0, v.x,  fmaf(w1, v.y, fmaf(w2, v.z, bb)));
    o.z = fmaf(w0, v.y,  fmaf(w1, v.z, fmaf(w2, v.w, bb)));
    o.w = fmaf(w0, v.z,  fmaf(w1, v.w, fmaf(w2, right, bb)));

    reinterpret_cast<float4*>(out)[gid] = o;
}

extern "C" void kernel_launch(void* const* d_in, const int* in_sizes, int n_in,
                              void* d_out, int out_size)
{
    const float* x    = (const float*)d_in[0];
    const float* w    = (const float*)d_in[1];
    const float* bias = (const float*)d_in[2];
    float* out        = (float*)d_out;

    const unsigned int total4 = (unsigned int)ROWS * LEN4; // 8,388,608
    const unsigned int blocks = total4 / NTHREADS;         // 32768

    dwconv1d_kernel<<<blocks, NTHREADS>>>(x, w, bias, out);
}